// round 15
// baseline (speedup 1.0000x reference)
#include <cuda_runtime.h>
#include <cuda_fp16.h>
#include <math.h>
#include <stdint.h>

// ============================================================================
// ILCMDecoder on GB300 (baseline-PTX tensor path: mma.sync HMMA fp16 +
// ldmatrix + cp.async; tcgen05 rejected by this harness's ptxas target).
//
// Round 15: ONE kernel. Roles by bid:
//   dec1(128, one m-block each) | ts2(128) | ts3(384) | gemm2 producers(512)
//   | gemm3 consumers(1536) | flow(256, fills consumer tail) | reduce(1)
// Counter gating (all spins on strictly lower bids): g_dec[mi], g_ts2,
// g_ts3, g_ready[mi], g_flow_done. bid 0 zeroes all counters (wave 1).
// ============================================================================

#define B_TOT   16384
#define B_HALF  8192
#define DIMZ    16
#define HDIM    64
#define DECH    1024
#define DIMX    3072
#define KTOT    1024
#define LOG2PI  1.8378770664093453f
#define MIN_STD 0.2f
#define CLAMP_V 1000000.0f

#define DEC_CTAS  128
#define TS2_CTAS  128          // 1024 tiles / 8 per block
#define TS3_CTAS  384          // 3072 tiles / 8 per block
#define G2_CTAS   512
#define G3_CTAS   1536
#define FLOW_CTAS 256

#define TS2_BASE  DEC_CTAS                    // 128
#define TS3_BASE  (TS2_BASE + TS2_CTAS)       // 256
#define PROD_BASE (TS3_BASE + TS3_CTAS)       // 640
#define CONS_BASE (PROD_BASE + G2_CTAS)       // 1152
#define FLOW_BASE (CONS_BASE + G3_CTAS)       // 2688
#define RED_BID   (FLOW_BASE + FLOW_CTAS)     // 2944

// ---------------- device scratch (allocation-free) ----------------
__device__ __half g_h1[(size_t)B_TOT * DECH];
__device__ __half g_h2[(size_t)B_TOT * DECH];
__device__ __half g_w2[(size_t)DECH * DECH];   // Wd2^T fp16 [N,K]
__device__ __half g_w3[(size_t)DIMX * DECH];   // Wd3^T fp16 [N,K]
__device__ float g_partial[FLOW_CTAS];
__device__ int   g_dec[128];
__device__ int   g_ready[128];
__device__ int   g_ts2, g_ts3, g_flow_done;

// ---------------- PTX helpers (baseline family features only) --------------
__device__ __forceinline__ uint32_t smem_u32(const void* p) {
    uint32_t a;
    asm("{ .reg .u64 t; cvta.to.shared.u64 t, %1; cvt.u32.u64 %0, t; }"
        : "=r"(a) : "l"(p));
    return a;
}

#define CP_ASYNC16(smem, gptr) \
    asm volatile("cp.async.cg.shared.global [%0], [%1], 16;" \
        :: "r"((uint32_t)(smem)), "l"(gptr) : "memory")
#define CP_COMMIT() asm volatile("cp.async.commit_group;" ::: "memory")
#define CP_WAIT2()  asm volatile("cp.async.wait_group 2;" ::: "memory")
#define CP_WAIT1()  asm volatile("cp.async.wait_group 1;" ::: "memory")
#define CP_WAIT0()  asm volatile("cp.async.wait_group 0;" ::: "memory")

__device__ __forceinline__ void ldsm_x4(uint32_t* r, uint32_t addr) {
    asm volatile("ldmatrix.sync.aligned.m8n8.x4.shared.b16 {%0,%1,%2,%3}, [%4];"
        : "=r"(r[0]), "=r"(r[1]), "=r"(r[2]), "=r"(r[3]) : "r"(addr));
}

__device__ __forceinline__ void mma_f16(float* d, const uint32_t* a, const uint32_t* b) {
    asm volatile(
        "mma.sync.aligned.m16n8k16.row.col.f32.f16.f16.f32 "
        "{%0,%1,%2,%3}, {%4,%5,%6,%7}, {%8,%9}, {%0,%1,%2,%3};"
        : "+f"(d[0]), "+f"(d[1]), "+f"(d[2]), "+f"(d[3])
        : "r"(a[0]), "r"(a[1]), "r"(a[2]), "r"(a[3]), "r"(b[0]), "r"(b[1]));
}

__device__ __forceinline__ int ld_acq(const int* p) {
    int v;
    asm volatile("ld.acquire.gpu.s32 %0, [%1];" : "=r"(v) : "l"(p) : "memory");
    return v;
}
__device__ __forceinline__ void red_release_add1(int* p) {
    asm volatile("red.release.gpu.global.add.s32 [%0], %1;" :: "l"(p), "r"(1) : "memory");
}

__device__ __forceinline__ float clean_clamp(float x) {
    if (isnan(x)) x = 0.0f;
    return fminf(fmaxf(x, -CLAMP_V), CLAMP_V);
}

__device__ __forceinline__ uint32_t sw128(uint32_t byte) {
    return byte ^ ((byte >> 3) & 0x70);
}

__device__ __forceinline__ uint32_t h2u(__half2 h) {
    return *(uint32_t*)&h;
}

__device__ __forceinline__ void pack_relu(const float* c, float bb0, float bb1,
                                          uint32_t* dst2) {
    float v0 = fmaxf(c[0] + bb0, 0.0f), v1 = fmaxf(c[1] + bb1, 0.0f);
    float v2 = fmaxf(c[2] + bb0, 0.0f), v3 = fmaxf(c[3] + bb1, 0.0f);
    dst2[0] = h2u(__floats2half2_rn(v0, v1));
    dst2[1] = h2u(__floats2half2_rn(v2, v3));
}

// ============================================================================
// GEMM core config
// ============================================================================
#define BK       64
#define NCHUNK  (KTOT / BK)       // 16
#define NT       256
#define A_OFF   0
#define B_OFF   16384
#define STG_BYTES 49152
#define NSTG    4
#define SMEM_DYN (NSTG * STG_BYTES + 1024)
#define GTHREADS 512

__device__ __forceinline__ void load_stage(
    uint32_t stg,
    const __half* __restrict__ A, const __half* __restrict__ B,
    int m0, int n0, int kBase, int tid)
{
    const int c16 = tid & 7;
    const int rg  = tid >> 3;       // 0..63
    const int kOff = kBase + c16 * 8;
#pragma unroll
    for (int j = 0; j < 2; j++) {
        int row = rg + j * 64;
        uint32_t sw = sw128((uint32_t)row * 128 + c16 * 16);
        CP_ASYNC16(stg + A_OFF + sw, A + (size_t)(m0 + row) * KTOT + kOff);
    }
#pragma unroll
    for (int j = 0; j < 4; j++) {
        int row = rg + j * 64;
        uint32_t sw = sw128((uint32_t)row * 128 + c16 * 16);
        CP_ASYNC16(stg + B_OFF + sw, B + (size_t)(n0 + row) * KTOT + kOff);
    }
}

template <int EPI>
__device__ __forceinline__ void run_gemm(
    const __half* __restrict__ A, const __half* __restrict__ B,
    const float* __restrict__ bias,
    float* __restrict__ Cf, __half* __restrict__ Ch,
    int Ntot, int m0, int n0, uint32_t sbase, int tid)
{
    const int warp = tid >> 5;
    const int lane = tid & 31;
    const int wm   = warp & 1;
    const int wn   = warp >> 1;

    const int lrow = lane & 7;
    const int quad = lane >> 3;
    const int aRow = wm * 64 + (quad & 1) * 8 + lrow;
    const int aKb  = (quad >> 1) * 16;
    const int bRow = wn * 32 + (quad >> 1) * 8 + lrow;
    const int bKb  = (quad & 1) * 16;

    uint32_t aSw[4], bSw[2];
#pragma unroll
    for (int i = 0; i < 4; i++)
        aSw[i] = sw128((uint32_t)(aRow + i * 16) * 128);
#pragma unroll
    for (int g = 0; g < 2; g++)
        bSw[g] = sw128((uint32_t)(bRow + g * 16) * 128);

    float acc[4][4][4];
#pragma unroll
    for (int i = 0; i < 4; i++)
#pragma unroll
        for (int j = 0; j < 4; j++)
#pragma unroll
            for (int q = 0; q < 4; q++) acc[i][j][q] = 0.0f;

    load_stage(sbase,                 A, B, m0, n0, 0,      tid); CP_COMMIT();
    load_stage(sbase + STG_BYTES,     A, B, m0, n0, BK,     tid); CP_COMMIT();
    load_stage(sbase + 2 * STG_BYTES, A, B, m0, n0, 2 * BK, tid); CP_COMMIT();

#pragma unroll 1
    for (int c = 0; c < NCHUNK; c++) {
        if (c < NCHUNK - 2)       { CP_WAIT2(); }
        else if (c == NCHUNK - 2) { CP_WAIT1(); }
        else                      { CP_WAIT0(); }
        __syncthreads();
        if (c + 3 < NCHUNK) {
            load_stage(sbase + ((c + 3) & 3) * STG_BYTES,
                       A, B, m0, n0, (c + 3) * BK, tid);
            CP_COMMIT();
        }
        const uint32_t stg = sbase + (c & 3) * STG_BYTES;

#pragma unroll
        for (int kk = 0; kk < 4; kk++) {
            uint32_t a_r[4][4], b_r[2][4];
            const uint32_t ko = (uint32_t)(kk * 32);
#pragma unroll
            for (int i = 0; i < 4; i++)
                ldsm_x4(a_r[i], stg + A_OFF + (aSw[i] ^ (ko + aKb)));
#pragma unroll
            for (int g = 0; g < 2; g++)
                ldsm_x4(b_r[g], stg + B_OFF + (bSw[g] ^ (ko + bKb)));
#pragma unroll
            for (int i = 0; i < 4; i++)
#pragma unroll
                for (int j = 0; j < 4; j++)
                    mma_f16(acc[i][j], a_r[i], &b_r[j >> 1][(j & 1) * 2]);
        }
    }

    const int er = lane >> 2;
    const int ec = (lane & 3) * 2;
#pragma unroll
    for (int i = 0; i < 4; i++) {
        int mrow = m0 + wm * 64 + i * 16 + er;
#pragma unroll
        for (int j = 0; j < 4; j++) {
            int n = n0 + wn * 32 + j * 8 + ec;
            float b0 = bias[n], b1 = bias[n + 1];
            float v0 = acc[i][j][0] + b0, v1 = acc[i][j][1] + b1;
            float v2 = acc[i][j][2] + b0, v3 = acc[i][j][3] + b1;
            size_t g0 = (size_t)mrow * Ntot + n;
            size_t g1 = (size_t)(mrow + 8) * Ntot + n;
            if (EPI == 0) {
                *(float2*)(Cf + g0) = make_float2(v0, v1);
                *(float2*)(Cf + g1) = make_float2(v2, v3);
            } else {
                __half2 p;
                p.x = __float2half_rn(fmaxf(v0, 0.0f));
                p.y = __float2half_rn(fmaxf(v1, 0.0f));
                *(__half2*)(Ch + g0) = p;
                p.x = __float2half_rn(fmaxf(v2, 0.0f));
                p.y = __float2half_rn(fmaxf(v3, 0.0f));
                *(__half2*)(Ch + g1) = p;
            }
        }
    }
}

// ============================================================================
// flow role: block = (dim i, 512 batch rows), 16 warps (unchanged from R14).
// ============================================================================
__device__ __forceinline__ void run_flow(
    const float* __restrict__ e1, const float* __restrict__ e2,
    const float* __restrict__ interv,
    const float* __restrict__ W1, const float* __restrict__ b1,
    const float* __restrict__ W2, const float* __restrict__ b2,
    const float* __restrict__ W3, const float* __restrict__ b3,
    int fb, char* fbase, uint32_t sbase, int tid)
{
    const int i  = fb >> 4;
    const int rb = (fb & 15) * 512;

    __half* sCtx = (__half*)(fbase);
    __half* sW1t = (__half*)(fbase + 16384);
    __half* sW2t = (__half*)(fbase + 18432);
    __half* sW3t = (__half*)(fbase + 26624);
    float*  sb1f = (float*)(fbase + 28672);
    float*  sb2f = (float*)(fbase + 28928);
    float*  sb3f = (float*)(fbase + 29184);
    float*  red  = (float*)(fbase + 29248);

    const uint32_t ctxB = sbase;
    const uint32_t w1B  = sbase + 16384;
    const uint32_t w2B  = sbase + 18432;
    const uint32_t w3B  = sbase + 26624;

    {
        const float* src = e1 + (size_t)(rb + tid) * DIMZ;
        __half* dst = sCtx + tid * 16;
#pragma unroll
        for (int d = 0; d < DIMZ; d++) {
            float v = src[d];
            if (d == i) v = 0.0f;
            dst[d] = __float2half_rn(v);
        }
    }
    for (int t = tid; t < DIMZ * HDIM; t += GTHREADS) {
        int n = t & 63, k = t >> 6;
        sW1t[n * 16 + k] = __float2half_rn(W1[i * DIMZ * HDIM + k * HDIM + n]);
    }
    for (int t = tid; t < HDIM * HDIM; t += GTHREADS) {
        int n = t & 63, k = t >> 6;
        uint32_t byte = (uint32_t)n * 128 + k * 2;
        *(__half*)((char*)sW2t + sw128(byte)) =
            __float2half_rn(W2[i * HDIM * HDIM + k * HDIM + n]);
    }
    if (tid < 512) ((uint32_t*)sW3t)[tid] = 0;
    if (tid < HDIM) { sb1f[tid] = b1[i * HDIM + tid]; sb2f[tid] = b2[i * HDIM + tid]; }
    if (tid < 2) sb3f[tid] = b3[i * 2 + tid];
    __syncthreads();
    if (tid < 128) {
        int k = tid >> 1, o = tid & 1;
        uint32_t byte = (uint32_t)o * 128 + k * 2;
        *(__half*)((char*)sW3t + sw128(byte)) =
            __float2half_rn(W3[i * HDIM * 2 + k * 2 + o]);
    }
    __syncthreads();

    const int lane = tid & 31;
    const int lrow = lane & 7;
    const int quad = lane >> 3;
    const int t4   = lane & 3;
    const int gr   = lane >> 2;
    const int mbase = (tid >> 5) * 32;
    const uint32_t kb = (uint32_t)(quad & 1) * 16;

    uint32_t aC[2][4];
#pragma unroll
    for (int it = 0; it < 2; it++)
        ldsm_x4(aC[it], ctxB + (uint32_t)(mbase + it * 16 + (quad & 1) * 8 + lrow) * 32
                              + (quad >> 1) * 16);
    uint32_t bW1[4][4];
#pragma unroll
    for (int nt2 = 0; nt2 < 4; nt2++)
        ldsm_x4(bW1[nt2], w1B + (uint32_t)(nt2 * 16 + (quad >> 1) * 8 + lrow) * 32
                               + (quad & 1) * 16);
    uint32_t a2[2][4][4];
#pragma unroll
    for (int it = 0; it < 2; it++)
#pragma unroll
        for (int nt = 0; nt < 8; nt++) {
            float c[4] = {0.f, 0.f, 0.f, 0.f};
            mma_f16(c, aC[it], &bW1[nt >> 1][(nt & 1) * 2]);
            pack_relu(c, sb1f[nt * 8 + 2 * t4], sb1f[nt * 8 + 2 * t4 + 1],
                      &a2[it][nt >> 1][(nt & 1) * 2]);
        }

    uint32_t bSw2[4];
#pragma unroll
    for (int nt2 = 0; nt2 < 4; nt2++)
        bSw2[nt2] = sw128((uint32_t)(nt2 * 16 + (quad >> 1) * 8 + lrow) * 128);
    float c2[2][8][4];
#pragma unroll
    for (int it = 0; it < 2; it++)
#pragma unroll
        for (int nt = 0; nt < 8; nt++)
#pragma unroll
            for (int q = 0; q < 4; q++) c2[it][nt][q] = 0.0f;
#pragma unroll
    for (int ks = 0; ks < 4; ks++) {
        uint32_t bW2[4][4];
#pragma unroll
        for (int nt2 = 0; nt2 < 4; nt2++)
            ldsm_x4(bW2[nt2], w2B + (bSw2[nt2] ^ ((uint32_t)ks * 32 + kb)));
#pragma unroll
        for (int it = 0; it < 2; it++)
#pragma unroll
            for (int nt = 0; nt < 8; nt++)
                mma_f16(c2[it][nt], a2[it][ks], &bW2[nt >> 1][(nt & 1) * 2]);
    }
    uint32_t a3[2][4][4];
#pragma unroll
    for (int it = 0; it < 2; it++)
#pragma unroll
        for (int nt = 0; nt < 8; nt++)
            pack_relu(c2[it][nt], sb2f[nt * 8 + 2 * t4], sb2f[nt * 8 + 2 * t4 + 1],
                      &a3[it][nt >> 1][(nt & 1) * 2]);

    const uint32_t w3Sw = sw128((uint32_t)((quad >> 1) * 8 + lrow) * 128);
    float c3[2][4];
#pragma unroll
    for (int it = 0; it < 2; it++)
#pragma unroll
        for (int q = 0; q < 4; q++) c3[it][q] = 0.0f;
#pragma unroll
    for (int ks = 0; ks < 4; ks++) {
        uint32_t bW3[4];
        ldsm_x4(bW3, w3B + (w3Sw ^ ((uint32_t)ks * 32 + kb)));
#pragma unroll
        for (int it = 0; it < 2; it++)
            mma_f16(c3[it], a3[it][ks], &bW3[0]);
    }

    float lpsum = 0.0f;
    if (t4 == 0) {
#pragma unroll
        for (int it = 0; it < 2; it++)
#pragma unroll
            for (int rr = 0; rr < 2; rr++) {
                int b = rb + mbase + it * 16 + rr * 8 + gr;
                float shift = c3[it][rr * 2 + 0] + sb3f[0];
                float pv1   = c3[it][rr * 2 + 1] + sb3f[1];
                float sp = fmaxf(pv1, 0.0f) + log1pf(expf(-fabsf(pv1)));
                float scale = sp + MIN_STD;
                float z = (e2[(size_t)b * DIMZ + i] - shift) / scale;
                z = clean_clamp(z);
                float mask = interv[(size_t)b * (DIMZ + 1) + 1 + i];
                float lp2 = (-0.5f * z * z - 0.5f * LOG2PI - logf(scale)) * mask;
                float e1i = e1[(size_t)b * DIMZ + i];
                float lp1 = clean_clamp(-0.5f * e1i * e1i - 0.5f * LOG2PI);
                lpsum += lp1 + lp2;
            }
    }
    red[tid] = lpsum;
    __syncthreads();
#pragma unroll
    for (int st = 256; st > 0; st >>= 1) {
        if (tid < st) red[tid] += red[tid + st];
        __syncthreads();
    }
    if (tid == 0) {
        g_partial[fb] = red[0];
        __threadfence();
        red_release_add1(&g_flow_done);
    }
}

// ============================================================================
// ts role: 512 threads = 2 x 256-thread tile workers, 4 iterations (8 tiles).
// ============================================================================
__device__ __forceinline__ void ts_tile(const float* __restrict__ W,
                                        __half* __restrict__ T,
                                        int K, int N, int t, int ntx,
                                        float* tile, int ltid) {
    int nb = (t % ntx) * 32, kb2 = (t / ntx) * 32;
    int tx = ltid & 31, ty0 = ltid >> 5;
    for (int i2 = ty0; i2 < 32; i2 += 8)
        tile[i2 * 33 + tx] = W[(size_t)(kb2 + i2) * N + nb + tx];
    __syncthreads();
    for (int i2 = ty0; i2 < 32; i2 += 8)
        T[(size_t)(nb + i2) * K + kb2 + tx] = __float2half_rn(tile[tx * 33 + i2]);
}

__device__ __forceinline__ void run_ts(const float* __restrict__ W,
                                       __half* __restrict__ T,
                                       int K, int N, int ntx,
                                       int tileBase, char* fbase, int tid) {
    const int half = tid >> 8;      // 0/1
    const int ltid = tid & 255;
    float* tile = (float*)(fbase + half * 4352);   // 32*33*4 = 4224, pad to 4352
#pragma unroll 1
    for (int it = 0; it < 4; it++) {
        ts_tile(W, T, K, N, tileBase + it * 2 + half, ntx, tile, ltid);
        __syncthreads();
    }
}

// ============================================================================
// THE kernel
// ============================================================================
__global__ __launch_bounds__(GTHREADS, 1)
void mega_kernel(const float* __restrict__ e1, const float* __restrict__ e2,
                 const float* __restrict__ interv,
                 const float* __restrict__ W1, const float* __restrict__ b1,
                 const float* __restrict__ W2, const float* __restrict__ b2,
                 const float* __restrict__ W3, const float* __restrict__ b3,
                 const float* __restrict__ Wd1, const float* __restrict__ bd1,
                 const float* __restrict__ Wd2, const float* __restrict__ Wd3,
                 const float* __restrict__ bd2, const float* __restrict__ bd3,
                 float* __restrict__ out, float* __restrict__ out_scalar)
{
    extern __shared__ char dsm[];
    const uint32_t dsm0 = smem_u32(dsm);
    const uint32_t sbase = (dsm0 + 1023) & ~1023u;
    char* fbase = dsm + (sbase - dsm0);
    const int tid = threadIdx.x;
    const int bid = blockIdx.x;

    if (bid < DEC_CTAS) {
        // ---- dec1: one 128-row m-block ----
        if (bid == 0) {      // wave-1 counter init (all readers start >= wave 2)
            if (tid < 128) { g_dec[tid] = 0; g_ready[tid] = 0; }
            else if (tid == 128) g_ts2 = 0;
            else if (tid == 129) g_ts3 = 0;
            else if (tid == 130) g_flow_done = 0;
            __threadfence();
        }
        const int mi = bid;
        const int rb = mi * 128;
        float* se = (float*)fbase;                 // [128][16]
        for (int t = tid; t < 128 * 16; t += GTHREADS) {
            int r = t >> 4, d = t & 15;
            int row = rb + r;
            se[t] = (row < B_HALF) ? e1[(size_t)row * DIMZ + d]
                                   : e2[(size_t)(row - B_HALF) * DIMZ + d];
        }
        __syncthreads();

        const int c0 = tid * 2;                    // 2 cols per thread
        float2 bv = *(const float2*)&bd1[c0];
#pragma unroll 1
        for (int gidx = 0; gidx < 16; gidx++) {    // 16 groups of 8 rows
            float acc[8][2];
#pragma unroll
            for (int r = 0; r < 8; r++) { acc[r][0] = bv.x; acc[r][1] = bv.y; }
#pragma unroll
            for (int d = 0; d < DIMZ; d++) {
                float2 w = *(const float2*)&Wd1[d * DECH + c0];
#pragma unroll
                for (int r = 0; r < 8; r++) {
                    float ed = se[(gidx * 8 + r) * 16 + d];
                    acc[r][0] = fmaf(ed, w.x, acc[r][0]);
                    acc[r][1] = fmaf(ed, w.y, acc[r][1]);
                }
            }
#pragma unroll
            for (int r = 0; r < 8; r++) {
                __half2 hv;
                hv.x = __float2half_rn(fmaxf(acc[r][0], 0.0f));
                hv.y = __float2half_rn(fmaxf(acc[r][1], 0.0f));
                *(__half2*)(g_h1 + (size_t)(rb + gidx * 8 + r) * DECH + c0) = hv;
            }
        }
        __threadfence();
        __syncthreads();
        if (tid == 0) red_release_add1(&g_dec[mi]);

    } else if (bid < TS3_BASE) {
        // ---- ts2: Wd2 -> g_w2 ----
        run_ts(Wd2, g_w2, DECH, DECH, DECH / 32, (bid - TS2_BASE) * 8, fbase, tid);
        __threadfence();
        __syncthreads();
        if (tid == 0) red_release_add1(&g_ts2);

    } else if (bid < PROD_BASE) {
        // ---- ts3: Wd3 -> g_w3 ----
        run_ts(Wd3, g_w3, DECH, DIMX, DIMX / 32, (bid - TS3_BASE) * 8, fbase, tid);
        __threadfence();
        __syncthreads();
        if (tid == 0) red_release_add1(&g_ts3);

    } else if (bid < CONS_BASE) {
        // ---- gemm2 producer ----
        const int b = bid - PROD_BASE;
        const int mi = b >> 2, ni = b & 3;
        if (tid == 0) {
            while (ld_acq(&g_ts2) < TS2_CTAS) __nanosleep(128);
            while (ld_acq(&g_dec[mi]) < 1) __nanosleep(128);
        }
        __syncthreads();
        run_gemm<1>(g_h1, g_w2, bd2, nullptr, g_h2, DECH,
                    mi * 128, ni * NT, sbase, tid);
        __threadfence();
        __syncthreads();
        if (tid == 0) red_release_add1(&g_ready[mi]);

    } else if (bid < FLOW_BASE) {
        // ---- gemm3 consumer ----
        const int b2 = bid - CONS_BASE;
        const int mi = b2 / 12, nj = b2 % 12;
        if (tid == 0) {
            while (ld_acq(&g_ts3) < TS3_CTAS) __nanosleep(128);
            while (ld_acq(&g_ready[mi]) < 4) __nanosleep(128);
        }
        __syncthreads();
        run_gemm<0>(g_h2, g_w3, bd3, out, nullptr, DIMX,
                    mi * 128, nj * NT, sbase, tid);

    } else if (bid < RED_BID) {
        // ---- flow (fills the consumer tail) ----
        run_flow(e1, e2, interv, W1, b1, W2, b2, W3, b3,
                 bid - FLOW_BASE, fbase, sbase, tid);

    } else {
        // ---- final log_p reduce ----
        if (tid == 0) {
            while (ld_acq(&g_flow_done) < FLOW_CTAS) __nanosleep(256);
        }
        __syncthreads();
        __shared__ float red2[512];
        red2[tid] = (tid < FLOW_CTAS) ? g_partial[tid] : 0.0f;
        __syncthreads();
#pragma unroll
        for (int st = 256; st > 0; st >>= 1) {
            if (tid < st) red2[tid] += red2[tid + st];
            __syncthreads();
        }
        if (tid == 0) {
            float log_p_I = -logf((float)(DIMZ + 1)) * (float)B_HALF;
            *out_scalar = red2[0] + log_p_I;
        }
    }
}

// ============================================================================
extern "C" void kernel_launch(void* const* d_in, const int* in_sizes, int n_in,
                              void* d_out, int out_size) {
    const float* e1  = (const float*)d_in[0];
    const float* e2  = (const float*)d_in[1];
    const float* itv = (const float*)d_in[2];
    const float* W1  = (const float*)d_in[3];
    const float* b1  = (const float*)d_in[4];
    const float* W2  = (const float*)d_in[5];
    const float* b2  = (const float*)d_in[6];
    const float* W3  = (const float*)d_in[7];
    const float* b3  = (const float*)d_in[8];
    const float* Wd1 = (const float*)d_in[9];
    const float* bd1 = (const float*)d_in[10];
    const float* Wd2 = (const float*)d_in[11];
    const float* bd2 = (const float*)d_in[12];
    const float* Wd3 = (const float*)d_in[13];
    const float* bd3 = (const float*)d_in[14];
    float* out = (float*)d_out;

    cudaFuncSetAttribute(mega_kernel, cudaFuncAttributeMaxDynamicSharedMemorySize, SMEM_DYN);

    mega_kernel<<<RED_BID + 1, GTHREADS, SMEM_DYN>>>(
        e1, e2, itv, W1, b1, W2, b2, W3, b3,
        Wd1, bd1, Wd2, Wd3, bd2, bd3,
        out, out + ((size_t)out_size - 1));
}

// round 16
// speedup vs baseline: 1.0561x; 1.0561x over previous
#include <cuda_runtime.h>
#include <cuda_fp16.h>
#include <math.h>
#include <stdint.h>

// ============================================================================
// ILCMDecoder on GB300 (baseline-PTX tensor path: mma.sync HMMA fp16 +
// ldmatrix + cp.async; tcgen05 rejected by this harness's ptxas target).
//
// Round 16: R14 structure, flow moved to the TAIL of gemm_fused
// (producers | consumers | flow | reduce) so it fills the consumer
// wave-down ramp instead of delaying the GEMM head.
// ============================================================================

#define B_TOT   16384
#define B_HALF  8192
#define DIMZ    16
#define HDIM    64
#define DECH    1024
#define DIMX    3072
#define KTOT    1024
#define LOG2PI  1.8378770664093453f
#define MIN_STD 0.2f
#define CLAMP_V 1000000.0f

#define G2_CTAS   512           // gemm2: 128 m-tiles x 4 n-tiles
#define G3_CTAS   1536          // gemm3: 128 m-tiles x 12 n-tiles
#define FLOW_CTAS 256           // 16 dims x 16 chunks (512 rows each)
#define PROD_BASE 0
#define CONS_BASE G2_CTAS                      // 512
#define FLOW_BASE (G2_CTAS + G3_CTAS)          // 2048
#define RED_BID   (FLOW_BASE + FLOW_CTAS)      // 2304

// prep_light roles: dec1 (2048) | ts3 (3072) | ts2 (1024)
#define PL_TS3    2048
#define PL_TS2    (PL_TS3 + 3072)
#define PL_TOTAL  (PL_TS2 + 1024)

// ---------------- device scratch (allocation-free) ----------------
__device__ __half g_h1[(size_t)B_TOT * DECH];
__device__ __half g_h2[(size_t)B_TOT * DECH];
__device__ __half g_w2[(size_t)DECH * DECH];   // Wd2^T fp16 [N,K]
__device__ __half g_w3[(size_t)DIMX * DECH];   // Wd3^T fp16 [N,K]
__device__ float g_partial[FLOW_CTAS];
__device__ int   g_ready[128];                 // per-m-block h2 readiness (0..4)
__device__ int   g_flow_done;                  // flow CTA completion counter

// ---------------- PTX helpers (baseline family features only) --------------
__device__ __forceinline__ uint32_t smem_u32(const void* p) {
    uint32_t a;
    asm("{ .reg .u64 t; cvta.to.shared.u64 t, %1; cvt.u32.u64 %0, t; }"
        : "=r"(a) : "l"(p));
    return a;
}

#define CP_ASYNC16(smem, gptr) \
    asm volatile("cp.async.cg.shared.global [%0], [%1], 16;" \
        :: "r"((uint32_t)(smem)), "l"(gptr) : "memory")
#define CP_COMMIT() asm volatile("cp.async.commit_group;" ::: "memory")
#define CP_WAIT2()  asm volatile("cp.async.wait_group 2;" ::: "memory")
#define CP_WAIT1()  asm volatile("cp.async.wait_group 1;" ::: "memory")
#define CP_WAIT0()  asm volatile("cp.async.wait_group 0;" ::: "memory")

__device__ __forceinline__ void ldsm_x4(uint32_t* r, uint32_t addr) {
    asm volatile("ldmatrix.sync.aligned.m8n8.x4.shared.b16 {%0,%1,%2,%3}, [%4];"
        : "=r"(r[0]), "=r"(r[1]), "=r"(r[2]), "=r"(r[3]) : "r"(addr));
}

__device__ __forceinline__ void mma_f16(float* d, const uint32_t* a, const uint32_t* b) {
    asm volatile(
        "mma.sync.aligned.m16n8k16.row.col.f32.f16.f16.f32 "
        "{%0,%1,%2,%3}, {%4,%5,%6,%7}, {%8,%9}, {%0,%1,%2,%3};"
        : "+f"(d[0]), "+f"(d[1]), "+f"(d[2]), "+f"(d[3])
        : "r"(a[0]), "r"(a[1]), "r"(a[2]), "r"(a[3]), "r"(b[0]), "r"(b[1]));
}

__device__ __forceinline__ int ld_acq(const int* p) {
    int v;
    asm volatile("ld.acquire.gpu.s32 %0, [%1];" : "=r"(v) : "l"(p) : "memory");
    return v;
}
__device__ __forceinline__ void red_release_add1(int* p) {
    asm volatile("red.release.gpu.global.add.s32 [%0], %1;" :: "l"(p), "r"(1) : "memory");
}

__device__ __forceinline__ float clean_clamp(float x) {
    if (isnan(x)) x = 0.0f;
    return fminf(fmaxf(x, -CLAMP_V), CLAMP_V);
}

__device__ __forceinline__ uint32_t sw128(uint32_t byte) {
    return byte ^ ((byte >> 3) & 0x70);
}

__device__ __forceinline__ uint32_t h2u(__half2 h) {
    return *(uint32_t*)&h;
}

__device__ __forceinline__ void pack_relu(const float* c, float bb0, float bb1,
                                          uint32_t* dst2) {
    float v0 = fmaxf(c[0] + bb0, 0.0f), v1 = fmaxf(c[1] + bb1, 0.0f);
    float v2 = fmaxf(c[2] + bb0, 0.0f), v3 = fmaxf(c[3] + bb1, 0.0f);
    dst2[0] = h2u(__floats2half2_rn(v0, v1));
    dst2[1] = h2u(__floats2half2_rn(v2, v3));
}

// ============================================================================
// prep_light: dec1 (2048 x 8 rows) | ts3 (3072) | ts2 (1024); (256,3).
// Also zeroes g_ready + g_flow_done (replay-safe).
// ============================================================================
__device__ __forceinline__ void do_tsplit(const float* __restrict__ W,
                                          __half* __restrict__ T,
                                          int K, int N, int t, int ntx,
                                          float* tile, int tid) {
    int nb = (t % ntx) * 32, kb2 = (t / ntx) * 32;
    int tx = tid & 31, ty0 = tid >> 5;
    for (int i2 = ty0; i2 < 32; i2 += 8)
        tile[i2 * 33 + tx] = W[(size_t)(kb2 + i2) * N + nb + tx];
    __syncthreads();
    for (int i2 = ty0; i2 < 32; i2 += 8)
        T[(size_t)(nb + i2) * K + kb2 + tx] = __float2half_rn(tile[tx * 33 + i2]);
}

__global__ __launch_bounds__(256, 3)
void prep_light(const float* __restrict__ e1, const float* __restrict__ e2,
                const float* __restrict__ Wd1, const float* __restrict__ bd1,
                const float* __restrict__ Wd2, const float* __restrict__ Wd3)
{
    __shared__ __align__(16) float smbuf[32 * 33];
    const int bid = blockIdx.x;
    const int tid = threadIdx.x;

    if (bid < PL_TS3) {
        // dec1: 8 rows of H1 = relu(E@Wd1+bd1)
        if (bid < 128 && tid == 0) g_ready[bid] = 0;
        if (bid == 0 && tid == 32) g_flow_done = 0;

        const int rb = bid * 8;
        float* se = smbuf;   // [8][16]
        if (tid < 128) {
            int r = tid >> 4, d = tid & 15;
            int row = rb + r;
            se[tid] = (row < B_HALF) ? e1[(size_t)row * DIMZ + d]
                                     : e2[(size_t)(row - B_HALF) * DIMZ + d];
        }
        __syncthreads();

        const int c0 = tid * 4;
        float4 bv = *(const float4*)&bd1[c0];
        float acc[8][4];
#pragma unroll
        for (int r = 0; r < 8; r++) {
            acc[r][0] = bv.x; acc[r][1] = bv.y; acc[r][2] = bv.z; acc[r][3] = bv.w;
        }
#pragma unroll
        for (int d = 0; d < DIMZ; d++) {
            float4 w = *(const float4*)&Wd1[d * DECH + c0];
#pragma unroll
            for (int r = 0; r < 8; r++) {
                float ed = se[r * 16 + d];
                acc[r][0] = fmaf(ed, w.x, acc[r][0]);
                acc[r][1] = fmaf(ed, w.y, acc[r][1]);
                acc[r][2] = fmaf(ed, w.z, acc[r][2]);
                acc[r][3] = fmaf(ed, w.w, acc[r][3]);
            }
        }
#pragma unroll
        for (int r = 0; r < 8; r++) {
            __half2 ha, hb;
            ha.x = __float2half_rn(fmaxf(acc[r][0], 0.0f));
            ha.y = __float2half_rn(fmaxf(acc[r][1], 0.0f));
            hb.x = __float2half_rn(fmaxf(acc[r][2], 0.0f));
            hb.y = __float2half_rn(fmaxf(acc[r][3], 0.0f));
            __half* dst = g_h1 + (size_t)(rb + r) * DECH + c0;
            *(__half2*)(dst)     = ha;
            *(__half2*)(dst + 2) = hb;
        }
    } else if (bid < PL_TS2) {
        do_tsplit(Wd3, g_w3, DECH, DIMX, bid - PL_TS3, DIMX / 32, smbuf, tid);
    } else {
        do_tsplit(Wd2, g_w2, DECH, DECH, bid - PL_TS2, DECH / 32, smbuf, tid);
    }
}

// ============================================================================
// fp16 HMMA GEMM core: 512 threads, 16 warps, warp tile 64x32,
// CTA tile 128x256, BK=64, 4-stage cp.async pipeline.
// ============================================================================
#define BK       64
#define NCHUNK  (KTOT / BK)       // 16
#define NT       256
#define A_OFF   0
#define B_OFF   16384             // A: 128 rows x 128B
#define STG_BYTES 49152           // A 16K + B 32K
#define NSTG    4
#define SMEM_DYN (NSTG * STG_BYTES + 1024)
#define GTHREADS 512

__device__ __forceinline__ void load_stage(
    uint32_t stg,
    const __half* __restrict__ A, const __half* __restrict__ B,
    int m0, int n0, int kBase, int tid)
{
    const int c16 = tid & 7;
    const int rg  = tid >> 3;       // 0..63
    const int kOff = kBase + c16 * 8;
#pragma unroll
    for (int j = 0; j < 2; j++) {
        int row = rg + j * 64;
        uint32_t sw = sw128((uint32_t)row * 128 + c16 * 16);
        CP_ASYNC16(stg + A_OFF + sw, A + (size_t)(m0 + row) * KTOT + kOff);
    }
#pragma unroll
    for (int j = 0; j < 4; j++) {
        int row = rg + j * 64;
        uint32_t sw = sw128((uint32_t)row * 128 + c16 * 16);
        CP_ASYNC16(stg + B_OFF + sw, B + (size_t)(n0 + row) * KTOT + kOff);
    }
}

template <int EPI>
__device__ __forceinline__ void run_gemm(
    const __half* __restrict__ A, const __half* __restrict__ B,
    const float* __restrict__ bias,
    float* __restrict__ Cf, __half* __restrict__ Ch,
    int Ntot, int m0, int n0, uint32_t sbase, int tid)
{
    const int warp = tid >> 5;
    const int lane = tid & 31;
    const int wm   = warp & 1;
    const int wn   = warp >> 1;

    const int lrow = lane & 7;
    const int quad = lane >> 3;
    const int aRow = wm * 64 + (quad & 1) * 8 + lrow;
    const int aKb  = (quad >> 1) * 16;
    const int bRow = wn * 32 + (quad >> 1) * 8 + lrow;
    const int bKb  = (quad & 1) * 16;

    uint32_t aSw[4], bSw[2];
#pragma unroll
    for (int i = 0; i < 4; i++)
        aSw[i] = sw128((uint32_t)(aRow + i * 16) * 128);
#pragma unroll
    for (int g = 0; g < 2; g++)
        bSw[g] = sw128((uint32_t)(bRow + g * 16) * 128);

    float acc[4][4][4];
#pragma unroll
    for (int i = 0; i < 4; i++)
#pragma unroll
        for (int j = 0; j < 4; j++)
#pragma unroll
            for (int q = 0; q < 4; q++) acc[i][j][q] = 0.0f;

    load_stage(sbase,                 A, B, m0, n0, 0,      tid); CP_COMMIT();
    load_stage(sbase + STG_BYTES,     A, B, m0, n0, BK,     tid); CP_COMMIT();
    load_stage(sbase + 2 * STG_BYTES, A, B, m0, n0, 2 * BK, tid); CP_COMMIT();

#pragma unroll 1
    for (int c = 0; c < NCHUNK; c++) {
        if (c < NCHUNK - 2)       { CP_WAIT2(); }
        else if (c == NCHUNK - 2) { CP_WAIT1(); }
        else                      { CP_WAIT0(); }
        __syncthreads();
        if (c + 3 < NCHUNK) {
            load_stage(sbase + ((c + 3) & 3) * STG_BYTES,
                       A, B, m0, n0, (c + 3) * BK, tid);
            CP_COMMIT();
        }
        const uint32_t stg = sbase + (c & 3) * STG_BYTES;

#pragma unroll
        for (int kk = 0; kk < 4; kk++) {
            uint32_t a_r[4][4], b_r[2][4];
            const uint32_t ko = (uint32_t)(kk * 32);
#pragma unroll
            for (int i = 0; i < 4; i++)
                ldsm_x4(a_r[i], stg + A_OFF + (aSw[i] ^ (ko + aKb)));
#pragma unroll
            for (int g = 0; g < 2; g++)
                ldsm_x4(b_r[g], stg + B_OFF + (bSw[g] ^ (ko + bKb)));
#pragma unroll
            for (int i = 0; i < 4; i++)
#pragma unroll
                for (int j = 0; j < 4; j++)
                    mma_f16(acc[i][j], a_r[i], &b_r[j >> 1][(j & 1) * 2]);
        }
    }

    const int er = lane >> 2;
    const int ec = (lane & 3) * 2;
#pragma unroll
    for (int i = 0; i < 4; i++) {
        int mrow = m0 + wm * 64 + i * 16 + er;
#pragma unroll
        for (int j = 0; j < 4; j++) {
            int n = n0 + wn * 32 + j * 8 + ec;
            float b0 = bias[n], b1 = bias[n + 1];
            float v0 = acc[i][j][0] + b0, v1 = acc[i][j][1] + b1;
            float v2 = acc[i][j][2] + b0, v3 = acc[i][j][3] + b1;
            size_t g0 = (size_t)mrow * Ntot + n;
            size_t g1 = (size_t)(mrow + 8) * Ntot + n;
            if (EPI == 0) {
                *(float2*)(Cf + g0) = make_float2(v0, v1);
                *(float2*)(Cf + g1) = make_float2(v2, v3);
            } else {
                __half2 p;
                p.x = __float2half_rn(fmaxf(v0, 0.0f));
                p.y = __float2half_rn(fmaxf(v1, 0.0f));
                *(__half2*)(Ch + g0) = p;
                p.x = __float2half_rn(fmaxf(v2, 0.0f));
                p.y = __float2half_rn(fmaxf(v3, 0.0f));
                *(__half2*)(Ch + g1) = p;
            }
        }
    }
}

// ============================================================================
// flow role: block = (dim i, 512 batch rows), 16 warps (unchanged from R14).
// ============================================================================
__device__ __forceinline__ void run_flow(
    const float* __restrict__ e1, const float* __restrict__ e2,
    const float* __restrict__ interv,
    const float* __restrict__ W1, const float* __restrict__ b1,
    const float* __restrict__ W2, const float* __restrict__ b2,
    const float* __restrict__ W3, const float* __restrict__ b3,
    int fb, char* fbase, uint32_t sbase, int tid)
{
    const int i  = fb >> 4;
    const int rb = (fb & 15) * 512;

    __half* sCtx = (__half*)(fbase);
    __half* sW1t = (__half*)(fbase + 16384);
    __half* sW2t = (__half*)(fbase + 18432);
    __half* sW3t = (__half*)(fbase + 26624);
    float*  sb1f = (float*)(fbase + 28672);
    float*  sb2f = (float*)(fbase + 28928);
    float*  sb3f = (float*)(fbase + 29184);
    float*  red  = (float*)(fbase + 29248);

    const uint32_t ctxB = sbase;
    const uint32_t w1B  = sbase + 16384;
    const uint32_t w2B  = sbase + 18432;
    const uint32_t w3B  = sbase + 26624;

    {
        const float* src = e1 + (size_t)(rb + tid) * DIMZ;
        __half* dst = sCtx + tid * 16;
#pragma unroll
        for (int d = 0; d < DIMZ; d++) {
            float v = src[d];
            if (d == i) v = 0.0f;
            dst[d] = __float2half_rn(v);
        }
    }
    for (int t = tid; t < DIMZ * HDIM; t += GTHREADS) {
        int n = t & 63, k = t >> 6;
        sW1t[n * 16 + k] = __float2half_rn(W1[i * DIMZ * HDIM + k * HDIM + n]);
    }
    for (int t = tid; t < HDIM * HDIM; t += GTHREADS) {
        int n = t & 63, k = t >> 6;
        uint32_t byte = (uint32_t)n * 128 + k * 2;
        *(__half*)((char*)sW2t + sw128(byte)) =
            __float2half_rn(W2[i * HDIM * HDIM + k * HDIM + n]);
    }
    if (tid < 512) ((uint32_t*)sW3t)[tid] = 0;
    if (tid < HDIM) { sb1f[tid] = b1[i * HDIM + tid]; sb2f[tid] = b2[i * HDIM + tid]; }
    if (tid < 2) sb3f[tid] = b3[i * 2 + tid];
    __syncthreads();
    if (tid < 128) {
        int k = tid >> 1, o = tid & 1;
        uint32_t byte = (uint32_t)o * 128 + k * 2;
        *(__half*)((char*)sW3t + sw128(byte)) =
            __float2half_rn(W3[i * HDIM * 2 + k * 2 + o]);
    }
    __syncthreads();

    const int lane = tid & 31;
    const int lrow = lane & 7;
    const int quad = lane >> 3;
    const int t4   = lane & 3;
    const int gr   = lane >> 2;
    const int mbase = (tid >> 5) * 32;
    const uint32_t kb = (uint32_t)(quad & 1) * 16;

    uint32_t aC[2][4];
#pragma unroll
    for (int it = 0; it < 2; it++)
        ldsm_x4(aC[it], ctxB + (uint32_t)(mbase + it * 16 + (quad & 1) * 8 + lrow) * 32
                              + (quad >> 1) * 16);
    uint32_t bW1[4][4];
#pragma unroll
    for (int nt2 = 0; nt2 < 4; nt2++)
        ldsm_x4(bW1[nt2], w1B + (uint32_t)(nt2 * 16 + (quad >> 1) * 8 + lrow) * 32
                               + (quad & 1) * 16);
    uint32_t a2[2][4][4];
#pragma unroll
    for (int it = 0; it < 2; it++)
#pragma unroll
        for (int nt = 0; nt < 8; nt++) {
            float c[4] = {0.f, 0.f, 0.f, 0.f};
            mma_f16(c, aC[it], &bW1[nt >> 1][(nt & 1) * 2]);
            pack_relu(c, sb1f[nt * 8 + 2 * t4], sb1f[nt * 8 + 2 * t4 + 1],
                      &a2[it][nt >> 1][(nt & 1) * 2]);
        }

    uint32_t bSw2[4];
#pragma unroll
    for (int nt2 = 0; nt2 < 4; nt2++)
        bSw2[nt2] = sw128((uint32_t)(nt2 * 16 + (quad >> 1) * 8 + lrow) * 128);
    float c2[2][8][4];
#pragma unroll
    for (int it = 0; it < 2; it++)
#pragma unroll
        for (int nt = 0; nt < 8; nt++)
#pragma unroll
            for (int q = 0; q < 4; q++) c2[it][nt][q] = 0.0f;
#pragma unroll
    for (int ks = 0; ks < 4; ks++) {
        uint32_t bW2[4][4];
#pragma unroll
        for (int nt2 = 0; nt2 < 4; nt2++)
            ldsm_x4(bW2[nt2], w2B + (bSw2[nt2] ^ ((uint32_t)ks * 32 + kb)));
#pragma unroll
        for (int it = 0; it < 2; it++)
#pragma unroll
            for (int nt = 0; nt < 8; nt++)
                mma_f16(c2[it][nt], a2[it][ks], &bW2[nt >> 1][(nt & 1) * 2]);
    }
    uint32_t a3[2][4][4];
#pragma unroll
    for (int it = 0; it < 2; it++)
#pragma unroll
        for (int nt = 0; nt < 8; nt++)
            pack_relu(c2[it][nt], sb2f[nt * 8 + 2 * t4], sb2f[nt * 8 + 2 * t4 + 1],
                      &a3[it][nt >> 1][(nt & 1) * 2]);

    const uint32_t w3Sw = sw128((uint32_t)((quad >> 1) * 8 + lrow) * 128);
    float c3[2][4];
#pragma unroll
    for (int it = 0; it < 2; it++)
#pragma unroll
        for (int q = 0; q < 4; q++) c3[it][q] = 0.0f;
#pragma unroll
    for (int ks = 0; ks < 4; ks++) {
        uint32_t bW3[4];
        ldsm_x4(bW3, w3B + (w3Sw ^ ((uint32_t)ks * 32 + kb)));
#pragma unroll
        for (int it = 0; it < 2; it++)
            mma_f16(c3[it], a3[it][ks], &bW3[0]);
    }

    float lpsum = 0.0f;
    if (t4 == 0) {
#pragma unroll
        for (int it = 0; it < 2; it++)
#pragma unroll
            for (int rr = 0; rr < 2; rr++) {
                int b = rb + mbase + it * 16 + rr * 8 + gr;
                float shift = c3[it][rr * 2 + 0] + sb3f[0];
                float pv1   = c3[it][rr * 2 + 1] + sb3f[1];
                float sp = fmaxf(pv1, 0.0f) + log1pf(expf(-fabsf(pv1)));
                float scale = sp + MIN_STD;
                float z = (e2[(size_t)b * DIMZ + i] - shift) / scale;
                z = clean_clamp(z);
                float mask = interv[(size_t)b * (DIMZ + 1) + 1 + i];
                float lp2 = (-0.5f * z * z - 0.5f * LOG2PI - logf(scale)) * mask;
                float e1i = e1[(size_t)b * DIMZ + i];
                float lp1 = clean_clamp(-0.5f * e1i * e1i - 0.5f * LOG2PI);
                lpsum += lp1 + lp2;
            }
    }
    red[tid] = lpsum;
    __syncthreads();
#pragma unroll
    for (int st = 256; st > 0; st >>= 1) {
        if (tid < st) red[tid] += red[tid + st];
        __syncthreads();
    }
    if (tid == 0) {
        g_partial[fb] = red[0];
        __threadfence();
        red_release_add1(&g_flow_done);
    }
}

// ============================================================================
// gemm_fused: producers(0..511) | consumers(512..2047) | flow(2048..2303)
// | reduce(2304). All spins target strictly lower bids -> deadlock-free.
// ============================================================================
__global__ __launch_bounds__(GTHREADS, 1)
void gemm_fused(const float* __restrict__ e1, const float* __restrict__ e2,
                const float* __restrict__ interv,
                const float* __restrict__ W1, const float* __restrict__ b1,
                const float* __restrict__ W2, const float* __restrict__ b2,
                const float* __restrict__ W3, const float* __restrict__ b3,
                const float* __restrict__ bd2, const float* __restrict__ bd3,
                float* __restrict__ out, float* __restrict__ out_scalar)
{
    extern __shared__ char dsm[];
    const uint32_t dsm0 = smem_u32(dsm);
    const uint32_t sbase = (dsm0 + 1023) & ~1023u;
    const int tid = threadIdx.x;
    const int bid = blockIdx.x;

    if (bid < CONS_BASE) {
        const int mi = bid >> 2, ni = bid & 3;
        run_gemm<1>(g_h1, g_w2, bd2, nullptr, g_h2, DECH,
                    mi * 128, ni * NT, sbase, tid);
        __threadfence();
        __syncthreads();
        if (tid == 0) red_release_add1(&g_ready[mi]);
    } else if (bid < FLOW_BASE) {
        const int b2 = bid - CONS_BASE;
        const int mi = b2 / 12, nj = b2 % 12;
        if (tid == 0) {
            while (ld_acq(&g_ready[mi]) < 4) __nanosleep(128);
        }
        __syncthreads();
        run_gemm<0>(g_h2, g_w3, bd3, out, nullptr, DIMX,
                    mi * 128, nj * NT, sbase, tid);
    } else if (bid < RED_BID) {
        run_flow(e1, e2, interv, W1, b1, W2, b2, W3, b3,
                 bid - FLOW_BASE, dsm + (sbase - dsm0), sbase, tid);
    } else {
        if (tid == 0) {
            while (ld_acq(&g_flow_done) < FLOW_CTAS) __nanosleep(256);
        }
        __syncthreads();
        __shared__ float red2[512];
        red2[tid] = (tid < FLOW_CTAS) ? g_partial[tid] : 0.0f;
        __syncthreads();
#pragma unroll
        for (int st = 256; st > 0; st >>= 1) {
            if (tid < st) red2[tid] += red2[tid + st];
            __syncthreads();
        }
        if (tid == 0) {
            float log_p_I = -logf((float)(DIMZ + 1)) * (float)B_HALF;
            *out_scalar = red2[0] + log_p_I;
        }
    }
}

// ============================================================================
extern "C" void kernel_launch(void* const* d_in, const int* in_sizes, int n_in,
                              void* d_out, int out_size) {
    const float* e1  = (const float*)d_in[0];
    const float* e2  = (const float*)d_in[1];
    const float* itv = (const float*)d_in[2];
    const float* W1  = (const float*)d_in[3];
    const float* b1  = (const float*)d_in[4];
    const float* W2  = (const float*)d_in[5];
    const float* b2  = (const float*)d_in[6];
    const float* W3  = (const float*)d_in[7];
    const float* b3  = (const float*)d_in[8];
    const float* Wd1 = (const float*)d_in[9];
    const float* bd1 = (const float*)d_in[10];
    const float* Wd2 = (const float*)d_in[11];
    const float* bd2 = (const float*)d_in[12];
    const float* Wd3 = (const float*)d_in[13];
    const float* bd3 = (const float*)d_in[14];
    float* out = (float*)d_out;

    cudaFuncSetAttribute(gemm_fused, cudaFuncAttributeMaxDynamicSharedMemorySize, SMEM_DYN);

    // dec1 + weight transposes (+ counter zeroing)
    prep_light<<<PL_TOTAL, 256>>>(e1, e2, Wd1, bd1, Wd2, Wd3);

    // gemm2 + gemm3 + flow (tail) + log_p finalize, one launch
    gemm_fused<<<RED_BID + 1, GTHREADS, SMEM_DYN>>>(
        e1, e2, itv, W1, b1, W2, b2, W3, b3,
        bd2, bd3, out, out + ((size_t)out_size - 1));
}

// round 17
// speedup vs baseline: 1.0588x; 1.0026x over previous
#include <cuda_runtime.h>
#include <cuda_fp16.h>
#include <math.h>
#include <stdint.h>

// ============================================================================
// ILCMDecoder on GB300 (baseline-PTX tensor path: mma.sync HMMA fp16 +
// ldmatrix + cp.async; tcgen05 rejected by this harness's ptxas target).
//
// Round 17: dec1 reworked to 512 blocks x 32 rows (4 row-group loop) so
// Wd1 is L1-resident per block -> 4x less L2 traffic. Everything else
// identical to Round 16 (prep_light | gemm_fused with flow at tail).
// ============================================================================

#define B_TOT   16384
#define B_HALF  8192
#define DIMZ    16
#define HDIM    64
#define DECH    1024
#define DIMX    3072
#define KTOT    1024
#define LOG2PI  1.8378770664093453f
#define MIN_STD 0.2f
#define CLAMP_V 1000000.0f

#define G2_CTAS   512           // gemm2: 128 m-tiles x 4 n-tiles
#define G3_CTAS   1536          // gemm3: 128 m-tiles x 12 n-tiles
#define FLOW_CTAS 256           // 16 dims x 16 chunks (512 rows each)
#define PROD_BASE 0
#define CONS_BASE G2_CTAS                      // 512
#define FLOW_BASE (G2_CTAS + G3_CTAS)          // 2048
#define RED_BID   (FLOW_BASE + FLOW_CTAS)      // 2304

// prep_light roles: dec1 (512 x 32 rows) | ts3 (3072) | ts2 (1024)
#define PL_TS3    512
#define PL_TS2    (PL_TS3 + 3072)
#define PL_TOTAL  (PL_TS2 + 1024)

// ---------------- device scratch (allocation-free) ----------------
__device__ __half g_h1[(size_t)B_TOT * DECH];
__device__ __half g_h2[(size_t)B_TOT * DECH];
__device__ __half g_w2[(size_t)DECH * DECH];   // Wd2^T fp16 [N,K]
__device__ __half g_w3[(size_t)DIMX * DECH];   // Wd3^T fp16 [N,K]
__device__ float g_partial[FLOW_CTAS];
__device__ int   g_ready[128];                 // per-m-block h2 readiness (0..4)
__device__ int   g_flow_done;                  // flow CTA completion counter

// ---------------- PTX helpers (baseline family features only) --------------
__device__ __forceinline__ uint32_t smem_u32(const void* p) {
    uint32_t a;
    asm("{ .reg .u64 t; cvta.to.shared.u64 t, %1; cvt.u32.u64 %0, t; }"
        : "=r"(a) : "l"(p));
    return a;
}

#define CP_ASYNC16(smem, gptr) \
    asm volatile("cp.async.cg.shared.global [%0], [%1], 16;" \
        :: "r"((uint32_t)(smem)), "l"(gptr) : "memory")
#define CP_COMMIT() asm volatile("cp.async.commit_group;" ::: "memory")
#define CP_WAIT2()  asm volatile("cp.async.wait_group 2;" ::: "memory")
#define CP_WAIT1()  asm volatile("cp.async.wait_group 1;" ::: "memory")
#define CP_WAIT0()  asm volatile("cp.async.wait_group 0;" ::: "memory")

__device__ __forceinline__ void ldsm_x4(uint32_t* r, uint32_t addr) {
    asm volatile("ldmatrix.sync.aligned.m8n8.x4.shared.b16 {%0,%1,%2,%3}, [%4];"
        : "=r"(r[0]), "=r"(r[1]), "=r"(r[2]), "=r"(r[3]) : "r"(addr));
}

__device__ __forceinline__ void mma_f16(float* d, const uint32_t* a, const uint32_t* b) {
    asm volatile(
        "mma.sync.aligned.m16n8k16.row.col.f32.f16.f16.f32 "
        "{%0,%1,%2,%3}, {%4,%5,%6,%7}, {%8,%9}, {%0,%1,%2,%3};"
        : "+f"(d[0]), "+f"(d[1]), "+f"(d[2]), "+f"(d[3])
        : "r"(a[0]), "r"(a[1]), "r"(a[2]), "r"(a[3]), "r"(b[0]), "r"(b[1]));
}

__device__ __forceinline__ int ld_acq(const int* p) {
    int v;
    asm volatile("ld.acquire.gpu.s32 %0, [%1];" : "=r"(v) : "l"(p) : "memory");
    return v;
}
__device__ __forceinline__ void red_release_add1(int* p) {
    asm volatile("red.release.gpu.global.add.s32 [%0], %1;" :: "l"(p), "r"(1) : "memory");
}

__device__ __forceinline__ float clean_clamp(float x) {
    if (isnan(x)) x = 0.0f;
    return fminf(fmaxf(x, -CLAMP_V), CLAMP_V);
}

__device__ __forceinline__ uint32_t sw128(uint32_t byte) {
    return byte ^ ((byte >> 3) & 0x70);
}

__device__ __forceinline__ uint32_t h2u(__half2 h) {
    return *(uint32_t*)&h;
}

__device__ __forceinline__ void pack_relu(const float* c, float bb0, float bb1,
                                          uint32_t* dst2) {
    float v0 = fmaxf(c[0] + bb0, 0.0f), v1 = fmaxf(c[1] + bb1, 0.0f);
    float v2 = fmaxf(c[2] + bb0, 0.0f), v3 = fmaxf(c[3] + bb1, 0.0f);
    dst2[0] = h2u(__floats2half2_rn(v0, v1));
    dst2[1] = h2u(__floats2half2_rn(v2, v3));
}

// ============================================================================
// prep_light: dec1 (512 x 32 rows) | ts3 (3072) | ts2 (1024); (256,3).
// Also zeroes g_ready + g_flow_done (replay-safe).
// ============================================================================
__device__ __forceinline__ void do_tsplit(const float* __restrict__ W,
                                          __half* __restrict__ T,
                                          int K, int N, int t, int ntx,
                                          float* tile, int tid) {
    int nb = (t % ntx) * 32, kb2 = (t / ntx) * 32;
    int tx = tid & 31, ty0 = tid >> 5;
    for (int i2 = ty0; i2 < 32; i2 += 8)
        tile[i2 * 33 + tx] = W[(size_t)(kb2 + i2) * N + nb + tx];
    __syncthreads();
    for (int i2 = ty0; i2 < 32; i2 += 8)
        T[(size_t)(nb + i2) * K + kb2 + tx] = __float2half_rn(tile[tx * 33 + i2]);
}

__global__ __launch_bounds__(256, 3)
void prep_light(const float* __restrict__ e1, const float* __restrict__ e2,
                const float* __restrict__ Wd1, const float* __restrict__ bd1,
                const float* __restrict__ Wd2, const float* __restrict__ Wd3)
{
    __shared__ __align__(16) float smbuf[32 * 33];
    const int bid = blockIdx.x;
    const int tid = threadIdx.x;

    if (bid < PL_TS3) {
        // dec1: 32 rows of H1 = relu(E@Wd1+bd1), 4 row-groups (Wd1 L1-reuse)
        if (bid < 128 && tid == 0) g_ready[bid] = 0;
        if (bid == 0 && tid == 32) g_flow_done = 0;

        const int rb = bid * 32;
        float* se = smbuf;   // [32][16]
        for (int t = tid; t < 32 * 16; t += 256) {
            int r = t >> 4, d = t & 15;
            int row = rb + r;
            se[t] = (row < B_HALF) ? e1[(size_t)row * DIMZ + d]
                                   : e2[(size_t)(row - B_HALF) * DIMZ + d];
        }
        __syncthreads();

        const int c0 = tid * 4;
        float4 bv = *(const float4*)&bd1[c0];
#pragma unroll 1
        for (int g = 0; g < 4; g++) {
            float acc[8][4];
#pragma unroll
            for (int r = 0; r < 8; r++) {
                acc[r][0] = bv.x; acc[r][1] = bv.y; acc[r][2] = bv.z; acc[r][3] = bv.w;
            }
#pragma unroll
            for (int d = 0; d < DIMZ; d++) {
                float4 w = *(const float4*)&Wd1[d * DECH + c0];
#pragma unroll
                for (int r = 0; r < 8; r++) {
                    float ed = se[(g * 8 + r) * 16 + d];
                    acc[r][0] = fmaf(ed, w.x, acc[r][0]);
                    acc[r][1] = fmaf(ed, w.y, acc[r][1]);
                    acc[r][2] = fmaf(ed, w.z, acc[r][2]);
                    acc[r][3] = fmaf(ed, w.w, acc[r][3]);
                }
            }
#pragma unroll
            for (int r = 0; r < 8; r++) {
                __half2 ha, hb;
                ha.x = __float2half_rn(fmaxf(acc[r][0], 0.0f));
                ha.y = __float2half_rn(fmaxf(acc[r][1], 0.0f));
                hb.x = __float2half_rn(fmaxf(acc[r][2], 0.0f));
                hb.y = __float2half_rn(fmaxf(acc[r][3], 0.0f));
                __half* dst = g_h1 + (size_t)(rb + g * 8 + r) * DECH + c0;
                *(__half2*)(dst)     = ha;
                *(__half2*)(dst + 2) = hb;
            }
        }
    } else if (bid < PL_TS2) {
        do_tsplit(Wd3, g_w3, DECH, DIMX, bid - PL_TS3, DIMX / 32, smbuf, tid);
    } else {
        do_tsplit(Wd2, g_w2, DECH, DECH, bid - PL_TS2, DECH / 32, smbuf, tid);
    }
}

// ============================================================================
// fp16 HMMA GEMM core: 512 threads, 16 warps, warp tile 64x32,
// CTA tile 128x256, BK=64, 4-stage cp.async pipeline. (UNCHANGED)
// ============================================================================
#define BK       64
#define NCHUNK  (KTOT / BK)       // 16
#define NT       256
#define A_OFF   0
#define B_OFF   16384             // A: 128 rows x 128B
#define STG_BYTES 49152           // A 16K + B 32K
#define NSTG    4
#define SMEM_DYN (NSTG * STG_BYTES + 1024)
#define GTHREADS 512

__device__ __forceinline__ void load_stage(
    uint32_t stg,
    const __half* __restrict__ A, const __half* __restrict__ B,
    int m0, int n0, int kBase, int tid)
{
    const int c16 = tid & 7;
    const int rg  = tid >> 3;       // 0..63
    const int kOff = kBase + c16 * 8;
#pragma unroll
    for (int j = 0; j < 2; j++) {
        int row = rg + j * 64;
        uint32_t sw = sw128((uint32_t)row * 128 + c16 * 16);
        CP_ASYNC16(stg + A_OFF + sw, A + (size_t)(m0 + row) * KTOT + kOff);
    }
#pragma unroll
    for (int j = 0; j < 4; j++) {
        int row = rg + j * 64;
        uint32_t sw = sw128((uint32_t)row * 128 + c16 * 16);
        CP_ASYNC16(stg + B_OFF + sw, B + (size_t)(n0 + row) * KTOT + kOff);
    }
}

template <int EPI>
__device__ __forceinline__ void run_gemm(
    const __half* __restrict__ A, const __half* __restrict__ B,
    const float* __restrict__ bias,
    float* __restrict__ Cf, __half* __restrict__ Ch,
    int Ntot, int m0, int n0, uint32_t sbase, int tid)
{
    const int warp = tid >> 5;
    const int lane = tid & 31;
    const int wm   = warp & 1;
    const int wn   = warp >> 1;

    const int lrow = lane & 7;
    const int quad = lane >> 3;
    const int aRow = wm * 64 + (quad & 1) * 8 + lrow;
    const int aKb  = (quad >> 1) * 16;
    const int bRow = wn * 32 + (quad >> 1) * 8 + lrow;
    const int bKb  = (quad & 1) * 16;

    uint32_t aSw[4], bSw[2];
#pragma unroll
    for (int i = 0; i < 4; i++)
        aSw[i] = sw128((uint32_t)(aRow + i * 16) * 128);
#pragma unroll
    for (int g = 0; g < 2; g++)
        bSw[g] = sw128((uint32_t)(bRow + g * 16) * 128);

    float acc[4][4][4];
#pragma unroll
    for (int i = 0; i < 4; i++)
#pragma unroll
        for (int j = 0; j < 4; j++)
#pragma unroll
            for (int q = 0; q < 4; q++) acc[i][j][q] = 0.0f;

    load_stage(sbase,                 A, B, m0, n0, 0,      tid); CP_COMMIT();
    load_stage(sbase + STG_BYTES,     A, B, m0, n0, BK,     tid); CP_COMMIT();
    load_stage(sbase + 2 * STG_BYTES, A, B, m0, n0, 2 * BK, tid); CP_COMMIT();

#pragma unroll 1
    for (int c = 0; c < NCHUNK; c++) {
        if (c < NCHUNK - 2)       { CP_WAIT2(); }
        else if (c == NCHUNK - 2) { CP_WAIT1(); }
        else                      { CP_WAIT0(); }
        __syncthreads();
        if (c + 3 < NCHUNK) {
            load_stage(sbase + ((c + 3) & 3) * STG_BYTES,
                       A, B, m0, n0, (c + 3) * BK, tid);
            CP_COMMIT();
        }
        const uint32_t stg = sbase + (c & 3) * STG_BYTES;

#pragma unroll
        for (int kk = 0; kk < 4; kk++) {
            uint32_t a_r[4][4], b_r[2][4];
            const uint32_t ko = (uint32_t)(kk * 32);
#pragma unroll
            for (int i = 0; i < 4; i++)
                ldsm_x4(a_r[i], stg + A_OFF + (aSw[i] ^ (ko + aKb)));
#pragma unroll
            for (int g = 0; g < 2; g++)
                ldsm_x4(b_r[g], stg + B_OFF + (bSw[g] ^ (ko + bKb)));
#pragma unroll
            for (int i = 0; i < 4; i++)
#pragma unroll
                for (int j = 0; j < 4; j++)
                    mma_f16(acc[i][j], a_r[i], &b_r[j >> 1][(j & 1) * 2]);
        }
    }

    const int er = lane >> 2;
    const int ec = (lane & 3) * 2;
#pragma unroll
    for (int i = 0; i < 4; i++) {
        int mrow = m0 + wm * 64 + i * 16 + er;
#pragma unroll
        for (int j = 0; j < 4; j++) {
            int n = n0 + wn * 32 + j * 8 + ec;
            float b0 = bias[n], b1 = bias[n + 1];
            float v0 = acc[i][j][0] + b0, v1 = acc[i][j][1] + b1;
            float v2 = acc[i][j][2] + b0, v3 = acc[i][j][3] + b1;
            size_t g0 = (size_t)mrow * Ntot + n;
            size_t g1 = (size_t)(mrow + 8) * Ntot + n;
            if (EPI == 0) {
                *(float2*)(Cf + g0) = make_float2(v0, v1);
                *(float2*)(Cf + g1) = make_float2(v2, v3);
            } else {
                __half2 p;
                p.x = __float2half_rn(fmaxf(v0, 0.0f));
                p.y = __float2half_rn(fmaxf(v1, 0.0f));
                *(__half2*)(Ch + g0) = p;
                p.x = __float2half_rn(fmaxf(v2, 0.0f));
                p.y = __float2half_rn(fmaxf(v3, 0.0f));
                *(__half2*)(Ch + g1) = p;
            }
        }
    }
}

// ============================================================================
// flow role: block = (dim i, 512 batch rows), 16 warps (UNCHANGED).
// ============================================================================
__device__ __forceinline__ void run_flow(
    const float* __restrict__ e1, const float* __restrict__ e2,
    const float* __restrict__ interv,
    const float* __restrict__ W1, const float* __restrict__ b1,
    const float* __restrict__ W2, const float* __restrict__ b2,
    const float* __restrict__ W3, const float* __restrict__ b3,
    int fb, char* fbase, uint32_t sbase, int tid)
{
    const int i  = fb >> 4;
    const int rb = (fb & 15) * 512;

    __half* sCtx = (__half*)(fbase);
    __half* sW1t = (__half*)(fbase + 16384);
    __half* sW2t = (__half*)(fbase + 18432);
    __half* sW3t = (__half*)(fbase + 26624);
    float*  sb1f = (float*)(fbase + 28672);
    float*  sb2f = (float*)(fbase + 28928);
    float*  sb3f = (float*)(fbase + 29184);
    float*  red  = (float*)(fbase + 29248);

    const uint32_t ctxB = sbase;
    const uint32_t w1B  = sbase + 16384;
    const uint32_t w2B  = sbase + 18432;
    const uint32_t w3B  = sbase + 26624;

    {
        const float* src = e1 + (size_t)(rb + tid) * DIMZ;
        __half* dst = sCtx + tid * 16;
#pragma unroll
        for (int d = 0; d < DIMZ; d++) {
            float v = src[d];
            if (d == i) v = 0.0f;
            dst[d] = __float2half_rn(v);
        }
    }
    for (int t = tid; t < DIMZ * HDIM; t += GTHREADS) {
        int n = t & 63, k = t >> 6;
        sW1t[n * 16 + k] = __float2half_rn(W1[i * DIMZ * HDIM + k * HDIM + n]);
    }
    for (int t = tid; t < HDIM * HDIM; t += GTHREADS) {
        int n = t & 63, k = t >> 6;
        uint32_t byte = (uint32_t)n * 128 + k * 2;
        *(__half*)((char*)sW2t + sw128(byte)) =
            __float2half_rn(W2[i * HDIM * HDIM + k * HDIM + n]);
    }
    if (tid < 512) ((uint32_t*)sW3t)[tid] = 0;
    if (tid < HDIM) { sb1f[tid] = b1[i * HDIM + tid]; sb2f[tid] = b2[i * HDIM + tid]; }
    if (tid < 2) sb3f[tid] = b3[i * 2 + tid];
    __syncthreads();
    if (tid < 128) {
        int k = tid >> 1, o = tid & 1;
        uint32_t byte = (uint32_t)o * 128 + k * 2;
        *(__half*)((char*)sW3t + sw128(byte)) =
            __float2half_rn(W3[i * HDIM * 2 + k * 2 + o]);
    }
    __syncthreads();

    const int lane = tid & 31;
    const int lrow = lane & 7;
    const int quad = lane >> 3;
    const int t4   = lane & 3;
    const int gr   = lane >> 2;
    const int mbase = (tid >> 5) * 32;
    const uint32_t kb = (uint32_t)(quad & 1) * 16;

    uint32_t aC[2][4];
#pragma unroll
    for (int it = 0; it < 2; it++)
        ldsm_x4(aC[it], ctxB + (uint32_t)(mbase + it * 16 + (quad & 1) * 8 + lrow) * 32
                              + (quad >> 1) * 16);
    uint32_t bW1[4][4];
#pragma unroll
    for (int nt2 = 0; nt2 < 4; nt2++)
        ldsm_x4(bW1[nt2], w1B + (uint32_t)(nt2 * 16 + (quad >> 1) * 8 + lrow) * 32
                               + (quad & 1) * 16);
    uint32_t a2[2][4][4];
#pragma unroll
    for (int it = 0; it < 2; it++)
#pragma unroll
        for (int nt = 0; nt < 8; nt++) {
            float c[4] = {0.f, 0.f, 0.f, 0.f};
            mma_f16(c, aC[it], &bW1[nt >> 1][(nt & 1) * 2]);
            pack_relu(c, sb1f[nt * 8 + 2 * t4], sb1f[nt * 8 + 2 * t4 + 1],
                      &a2[it][nt >> 1][(nt & 1) * 2]);
        }

    uint32_t bSw2[4];
#pragma unroll
    for (int nt2 = 0; nt2 < 4; nt2++)
        bSw2[nt2] = sw128((uint32_t)(nt2 * 16 + (quad >> 1) * 8 + lrow) * 128);
    float c2[2][8][4];
#pragma unroll
    for (int it = 0; it < 2; it++)
#pragma unroll
        for (int nt = 0; nt < 8; nt++)
#pragma unroll
            for (int q = 0; q < 4; q++) c2[it][nt][q] = 0.0f;
#pragma unroll
    for (int ks = 0; ks < 4; ks++) {
        uint32_t bW2[4][4];
#pragma unroll
        for (int nt2 = 0; nt2 < 4; nt2++)
            ldsm_x4(bW2[nt2], w2B + (bSw2[nt2] ^ ((uint32_t)ks * 32 + kb)));
#pragma unroll
        for (int it = 0; it < 2; it++)
#pragma unroll
            for (int nt = 0; nt < 8; nt++)
                mma_f16(c2[it][nt], a2[it][ks], &bW2[nt >> 1][(nt & 1) * 2]);
    }
    uint32_t a3[2][4][4];
#pragma unroll
    for (int it = 0; it < 2; it++)
#pragma unroll
        for (int nt = 0; nt < 8; nt++)
            pack_relu(c2[it][nt], sb2f[nt * 8 + 2 * t4], sb2f[nt * 8 + 2 * t4 + 1],
                      &a3[it][nt >> 1][(nt & 1) * 2]);

    const uint32_t w3Sw = sw128((uint32_t)((quad >> 1) * 8 + lrow) * 128);
    float c3[2][4];
#pragma unroll
    for (int it = 0; it < 2; it++)
#pragma unroll
        for (int q = 0; q < 4; q++) c3[it][q] = 0.0f;
#pragma unroll
    for (int ks = 0; ks < 4; ks++) {
        uint32_t bW3[4];
        ldsm_x4(bW3, w3B + (w3Sw ^ ((uint32_t)ks * 32 + kb)));
#pragma unroll
        for (int it = 0; it < 2; it++)
            mma_f16(c3[it], a3[it][ks], &bW3[0]);
    }

    float lpsum = 0.0f;
    if (t4 == 0) {
#pragma unroll
        for (int it = 0; it < 2; it++)
#pragma unroll
            for (int rr = 0; rr < 2; rr++) {
                int b = rb + mbase + it * 16 + rr * 8 + gr;
                float shift = c3[it][rr * 2 + 0] + sb3f[0];
                float pv1   = c3[it][rr * 2 + 1] + sb3f[1];
                float sp = fmaxf(pv1, 0.0f) + log1pf(expf(-fabsf(pv1)));
                float scale = sp + MIN_STD;
                float z = (e2[(size_t)b * DIMZ + i] - shift) / scale;
                z = clean_clamp(z);
                float mask = interv[(size_t)b * (DIMZ + 1) + 1 + i];
                float lp2 = (-0.5f * z * z - 0.5f * LOG2PI - logf(scale)) * mask;
                float e1i = e1[(size_t)b * DIMZ + i];
                float lp1 = clean_clamp(-0.5f * e1i * e1i - 0.5f * LOG2PI);
                lpsum += lp1 + lp2;
            }
    }
    red[tid] = lpsum;
    __syncthreads();
#pragma unroll
    for (int st = 256; st > 0; st >>= 1) {
        if (tid < st) red[tid] += red[tid + st];
        __syncthreads();
    }
    if (tid == 0) {
        g_partial[fb] = red[0];
        __threadfence();
        red_release_add1(&g_flow_done);
    }
}

// ============================================================================
// gemm_fused: producers(0..511) | consumers(512..2047) | flow(2048..2303)
// | reduce(2304). All spins target strictly lower bids -> deadlock-free.
// ============================================================================
__global__ __launch_bounds__(GTHREADS, 1)
void gemm_fused(const float* __restrict__ e1, const float* __restrict__ e2,
                const float* __restrict__ interv,
                const float* __restrict__ W1, const float* __restrict__ b1,
                const float* __restrict__ W2, const float* __restrict__ b2,
                const float* __restrict__ W3, const float* __restrict__ b3,
                const float* __restrict__ bd2, const float* __restrict__ bd3,
                float* __restrict__ out, float* __restrict__ out_scalar)
{
    extern __shared__ char dsm[];
    const uint32_t dsm0 = smem_u32(dsm);
    const uint32_t sbase = (dsm0 + 1023) & ~1023u;
    const int tid = threadIdx.x;
    const int bid = blockIdx.x;

    if (bid < CONS_BASE) {
        const int mi = bid >> 2, ni = bid & 3;
        run_gemm<1>(g_h1, g_w2, bd2, nullptr, g_h2, DECH,
                    mi * 128, ni * NT, sbase, tid);
        __threadfence();
        __syncthreads();
        if (tid == 0) red_release_add1(&g_ready[mi]);
    } else if (bid < FLOW_BASE) {
        const int b2 = bid - CONS_BASE;
        const int mi = b2 / 12, nj = b2 % 12;
        if (tid == 0) {
            while (ld_acq(&g_ready[mi]) < 4) __nanosleep(128);
        }
        __syncthreads();
        run_gemm<0>(g_h2, g_w3, bd3, out, nullptr, DIMX,
                    mi * 128, nj * NT, sbase, tid);
    } else if (bid < RED_BID) {
        run_flow(e1, e2, interv, W1, b1, W2, b2, W3, b3,
                 bid - FLOW_BASE, dsm + (sbase - dsm0), sbase, tid);
    } else {
        if (tid == 0) {
            while (ld_acq(&g_flow_done) < FLOW_CTAS) __nanosleep(256);
        }
        __syncthreads();
        __shared__ float red2[512];
        red2[tid] = (tid < FLOW_CTAS) ? g_partial[tid] : 0.0f;
        __syncthreads();
#pragma unroll
        for (int st = 256; st > 0; st >>= 1) {
            if (tid < st) red2[tid] += red2[tid + st];
            __syncthreads();
        }
        if (tid == 0) {
            float log_p_I = -logf((float)(DIMZ + 1)) * (float)B_HALF;
            *out_scalar = red2[0] + log_p_I;
        }
    }
}

// ============================================================================
extern "C" void kernel_launch(void* const* d_in, const int* in_sizes, int n_in,
                              void* d_out, int out_size) {
    const float* e1  = (const float*)d_in[0];
    const float* e2  = (const float*)d_in[1];
    const float* itv = (const float*)d_in[2];
    const float* W1  = (const float*)d_in[3];
    const float* b1  = (const float*)d_in[4];
    const float* W2  = (const float*)d_in[5];
    const float* b2  = (const float*)d_in[6];
    const float* W3  = (const float*)d_in[7];
    const float* b3  = (const float*)d_in[8];
    const float* Wd1 = (const float*)d_in[9];
    const float* bd1 = (const float*)d_in[10];
    const float* Wd2 = (const float*)d_in[11];
    const float* bd2 = (const float*)d_in[12];
    const float* Wd3 = (const float*)d_in[13];
    const float* bd3 = (const float*)d_in[14];
    float* out = (float*)d_out;

    cudaFuncSetAttribute(gemm_fused, cudaFuncAttributeMaxDynamicSharedMemorySize, SMEM_DYN);

    // dec1 + weight transposes (+ counter zeroing)
    prep_light<<<PL_TOTAL, 256>>>(e1, e2, Wd1, bd1, Wd2, Wd3);

    // gemm2 + gemm3 + flow (tail) + log_p finalize, one launch
    gemm_fused<<<RED_BID + 1, GTHREADS, SMEM_DYN>>>(
        e1, e2, itv, W1, b1, W2, b2, W3, b3,
        bd2, bd3, out, out + ((size_t)out_size - 1));
}